// round 2
// baseline (speedup 1.0000x reference)
#include <cuda_runtime.h>
#include <math.h>

// Problem constants
#define LEV     60
#define BATCH   4096
#define NXI     4
#define NH      64
#define NMEM    64
#define NSFC    17
#define NYO     4
#define XW1     68          // NXI + NMEM
#define KDIM    132         // unified K (rnn1: 68+64, rnn2: 64+64 zero-padded to 132)
#define NG      256         // 4*NH gate columns
#define NWCOL   320         // gates (256) + logvar (64)
#define TB      32          // batch rows per block
#define NTHREADS 256
#define NBLOCKS (BATCH / TB)   // 128

// shared layout (floats): W_s[NWCOL][KDIM] | xh[TB][KDIM] | gacc[TB][NWCOL]
#define SM_W     (NWCOL * KDIM)            // 42240
#define SM_XH    (TB * KDIM)               // 4224
#define SM_GACC  (TB * NWCOL)              // 10240
#define SMEM_FLOATS (SM_W + SM_XH + SM_GACC)
#define SMEM_BYTES  (SMEM_FLOATS * 4)      // 226816 < 232448 opt-in limit

// output layout: out (B,L,NYO) || out_sfc (B,3) || new_mem (B,L,NMEM)
#define OFF_OUT  0
#define OFF_SFC  (BATCH * LEV * NYO)                 // 983040
#define OFF_MEM  (OFF_SFC + BATCH * 3)               // 995328

// inter-phase scratch: rnn1out then (overwritten in place) rnn2out, [level][batch][NH]
__device__ float g_scratch[LEV * BATCH * NH];

struct Params {
    const float *inputs_main, *inputs_aux, *rnn1_mem, *eps1, *eps2, *eps_sfc;
    const float *W_sfc, *b_sfc, *W_sfc2, *b_sfc2, *W_toa, *b_toa, *W_toa2, *b_toa2;
    const float *Wx1, *Wh1, *Wxs1, *Whs1, *Wx2, *Wh2, *Wxs2, *Whs2;
    const float *W_lat, *b_lat, *W_out, *b_out, *W_sfcout, *b_sfcout;
    const float *W_mu, *b_mu, *W_lv, *b_lv;
    float *out;
};

__device__ __forceinline__ float sigmoidf_(float x) {
    return __fdividef(1.0f, 1.0f + __expf(-x));
}
__device__ __forceinline__ float tanhf_(float x) {
    float ax = fabsf(x);
    float e  = __expf(2.0f * ax);                    // overflow -> +inf -> term -> 0
    float t  = 1.0f - __fdividef(2.0f, e + 1.0f);
    return copysignf(t, x);
}

// Fused GEMM: gacc[r][j] = sum_k xh[r][k] * W_s[j][k], r<TB, j<NWCOL, K=KDIM.
// thread (tx = tid&63, ty = tid>>6) owns cols {c*64+tx} (c=0..4) x rows {ty*8+u} (u=0..7).
__device__ __forceinline__ void gemm_step(const float* __restrict__ W_s,
                                          const float* __restrict__ xh,
                                          float* __restrict__ gacc,
                                          int tx, int ty) {
    float acc[8][5];
#pragma unroll
    for (int u = 0; u < 8; u++)
#pragma unroll
        for (int c = 0; c < 5; c++) acc[u][c] = 0.0f;

    for (int kq = 0; kq < KDIM / 4; kq++) {
        float4 wv[5];
#pragma unroll
        for (int c = 0; c < 5; c++)
            wv[c] = *(const float4*)&W_s[(c * 64 + tx) * KDIM + kq * 4];
#pragma unroll
        for (int u = 0; u < 8; u++) {
            float4 xv = *(const float4*)&xh[(ty * 8 + u) * KDIM + kq * 4];
#pragma unroll
            for (int c = 0; c < 5; c++) {
                acc[u][c] = fmaf(xv.x, wv[c].x, acc[u][c]);
                acc[u][c] = fmaf(xv.y, wv[c].y, acc[u][c]);
                acc[u][c] = fmaf(xv.z, wv[c].z, acc[u][c]);
                acc[u][c] = fmaf(xv.w, wv[c].w, acc[u][c]);
            }
        }
    }
#pragma unroll
    for (int u = 0; u < 8; u++)
#pragma unroll
        for (int c = 0; c < 5; c++)
            gacc[(ty * 8 + u) * NWCOL + c * 64 + tx] = acc[u][c];
}

// LSTM pointwise for thread's 8 elems (row pr, cols pj0..pj0+7). c kept in regs.
__device__ __forceinline__ void pointwise_step(float* __restrict__ xh,
                                               const float* __restrict__ gacc,
                                               float* __restrict__ c_reg,
                                               int pr, int pj0, int hoff,
                                               const float* __restrict__ eps_ptr,
                                               float* __restrict__ hout_ptr) {
    const float* g = gacc + pr * NWCOL + pj0;
    float gi[8], gf[8], gg[8], go[8], gv[8], ge[8];
    *(float4*)&gi[0] = *(const float4*)(g);        *(float4*)&gi[4] = *(const float4*)(g + 4);
    *(float4*)&gf[0] = *(const float4*)(g + 64);   *(float4*)&gf[4] = *(const float4*)(g + 68);
    *(float4*)&gg[0] = *(const float4*)(g + 128);  *(float4*)&gg[4] = *(const float4*)(g + 132);
    *(float4*)&go[0] = *(const float4*)(g + 192);  *(float4*)&go[4] = *(const float4*)(g + 196);
    *(float4*)&gv[0] = *(const float4*)(g + 256);  *(float4*)&gv[4] = *(const float4*)(g + 260);
    *(float4*)&ge[0] = *(const float4*)(eps_ptr);  *(float4*)&ge[4] = *(const float4*)(eps_ptr + 4);

    float hs[8];
#pragma unroll
    for (int u = 0; u < 8; u++) {
        float iv = sigmoidf_(gi[u]);
        float fv = sigmoidf_(gf[u]);
        float gvv = tanhf_(gg[u]);
        float ov = sigmoidf_(go[u]);
        float c  = fv * c_reg[u] + iv * gvv;
        c_reg[u] = c;
        float h  = ov * tanhf_(c) + ge[u] * __expf(0.5f * gv[u]);
        xh[pr * KDIM + hoff + pj0 + u] = h;
        hs[u] = h;
    }
    *(float4*)(hout_ptr)     = *(const float4*)&hs[0];
    *(float4*)(hout_ptr + 4) = *(const float4*)&hs[4];
}

extern __shared__ float smem[];

__global__ __launch_bounds__(NTHREADS, 1)
void stochastic_rnn_kernel(Params p) {
    const int tid = threadIdx.x;
    const int b0  = blockIdx.x * TB;

    float* W_s  = smem;
    float* xh   = smem + SM_W;
    float* gacc = xh + SM_XH;

    // pointwise identity: (row pr, cols pj0..pj0+7)
    const int pr  = tid >> 3;
    const int pj0 = (tid & 7) * 8;
    // gemm identity
    const int tx = tid & 63;
    const int ty = tid >> 6;

    float c_reg[8];

    // ---------------- load rnn1 weights (transposed, fused) ----------------
    for (int idx = tid; idx < NWCOL * KDIM; idx += NTHREADS) {
        int j = idx / KDIM, k = idx % KDIM;
        float v;
        if (j < NG) v = (k < XW1) ? p.Wx1[k * NG + j] : p.Wh1[(k - XW1) * NG + j];
        else {
            int jj = j - NG;
            v = (k < XW1) ? p.Wxs1[k * NH + jj] : p.Whs1[(k - XW1) * NH + jj];
        }
        W_s[idx] = v;
    }

    // ---------------- rnn1 initial h, c from surface MLPs ----------------
    {
        const float* auxrow = p.inputs_aux + (size_t)(b0 + pr) * NSFC;
#pragma unroll
        for (int u = 0; u < 8; u++) {
            int j = pj0 + u;
            float ah = p.b_sfc[j], ac = p.b_sfc2[j];
            for (int k = 0; k < NSFC; k++) {
                float a = auxrow[k];
                ah = fmaf(a, p.W_sfc[k * NH + j], ah);
                ac = fmaf(a, p.W_sfc2[k * NH + j], ac);
            }
            xh[pr * KDIM + XW1 + j] = tanhf_(ah);
            c_reg[u] = tanhf_(ac);
        }
    }
    __syncthreads();

    // ---------------- rnn1: bottom-up over levels ----------------
    for (int s = 0; s < LEV; s++) {
        int l = LEV - 1 - s;
        for (int idx = tid; idx < TB * XW1; idx += NTHREADS) {
            int r = idx / XW1, k = idx % XW1;
            size_t b = b0 + r;
            float v = (k < NXI) ? p.inputs_main[(b * LEV + l) * NXI + k]
                                : p.rnn1_mem[(b * LEV + l) * NMEM + (k - NXI)];
            xh[r * KDIM + k] = v;
        }
        __syncthreads();
        gemm_step(W_s, xh, gacc, tx, ty);
        __syncthreads();
        pointwise_step(xh, gacc, c_reg, pr, pj0, XW1,
                       p.eps1 + ((size_t)s * BATCH + b0 + pr) * NH + pj0,
                       g_scratch + ((size_t)l * BATCH + b0 + pr) * NH + pj0);
        __syncthreads();
    }

    // ---------------- load rnn2 weights (K padded 128->132 with zeros) ----------------
    for (int idx = tid; idx < NWCOL * KDIM; idx += NTHREADS) {
        int j = idx / KDIM, k = idx % KDIM;
        float v = 0.0f;
        if (j < NG) {
            if (k < NH)            v = p.Wx2[k * NG + j];
            else if (k < 2 * NH)   v = p.Wh2[(k - NH) * NG + j];
        } else {
            int jj = j - NG;
            if (k < NH)            v = p.Wxs2[k * NH + jj];
            else if (k < 2 * NH)   v = p.Whs2[(k - NH) * NH + jj];
        }
        W_s[idx] = v;
    }
    // zero xh pad columns 128..131
    for (int idx = tid; idx < TB * 4; idx += NTHREADS)
        xh[(idx >> 2) * KDIM + 128 + (idx & 3)] = 0.0f;

    // rnn2 initial h, c from TOA MLPs (inputs_toa = aux[:,1], aux[:,6])
    {
        float x0 = p.inputs_aux[(size_t)(b0 + pr) * NSFC + 1];
        float x1 = p.inputs_aux[(size_t)(b0 + pr) * NSFC + 6];
#pragma unroll
        for (int u = 0; u < 8; u++) {
            int j = pj0 + u;
            float ah = fmaf(x0, p.W_toa[j],  fmaf(x1, p.W_toa[NH + j],  p.b_toa[j]));
            float ac = fmaf(x0, p.W_toa2[j], fmaf(x1, p.W_toa2[NH + j], p.b_toa2[j]));
            xh[pr * KDIM + NH + j] = tanhf_(ah);
            c_reg[u] = tanhf_(ac);
        }
    }
    __syncthreads();

    // ---------------- rnn2: top-down over levels; overwrite scratch in place ----------------
    for (int s = 0; s < LEV; s++) {
        for (int idx = tid; idx < TB * NH; idx += NTHREADS) {
            int r = idx >> 6, k = idx & 63;
            xh[r * KDIM + k] = g_scratch[((size_t)s * BATCH + b0 + r) * NH + k];
        }
        __syncthreads();
        gemm_step(W_s, xh, gacc, tx, ty);
        __syncthreads();
        pointwise_step(xh, gacc, c_reg, pr, pj0, NH,
                       p.eps2 + ((size_t)s * BATCH + b0 + pr) * NH + pj0,
                       g_scratch + ((size_t)s * BATCH + b0 + pr) * NH + pj0);
        __syncthreads();
    }

    // ---------------- surface heads from last hidden (in xh cols 64..127) ----------------
    if (tid < TB) {
        int r = tid;
        size_t b = b0 + r;
        float rad = p.b_sfcout[0];
        float mu0 = p.b_mu[0], mu1 = p.b_mu[1];
        float lv0 = p.b_lv[0], lv1 = p.b_lv[1];
        for (int k = 0; k < NH; k++) {
            float h = xh[r * KDIM + NH + k];
            rad = fmaf(h, p.W_sfcout[k], rad);
            mu0 = fmaf(h, p.W_mu[k * 2 + 0], mu0);
            mu1 = fmaf(h, p.W_mu[k * 2 + 1], mu1);
            lv0 = fmaf(h, p.W_lv[k * 2 + 0], lv0);
            lv1 = fmaf(h, p.W_lv[k * 2 + 1], lv1);
        }
        float e0 = p.eps_sfc[b * 2 + 0], e1 = p.eps_sfc[b * 2 + 1];
        p.out[OFF_SFC + b * 3 + 0] = mu0 + e0 * __expf(0.5f * lv0);
        p.out[OFF_SFC + b * 3 + 1] = mu1 + e1 * __expf(0.5f * lv1);
        p.out[OFF_SFC + b * 3 + 2] = rad;
    }

    // ---------------- load W_lat (transposed) + W_out/b_out into smem ----------------
    for (int idx = tid; idx < NH * NH; idx += NTHREADS) {
        int m = idx >> 6, k = idx & 63;
        W_s[m * KDIM + k] = p.W_lat[k * NH + m];
    }
    float* wout_s = W_s + NH * KDIM;         // 256 floats
    float* bout_s = wout_s + NH * NYO;       // 4 floats
    for (int idx = tid; idx < NH * NYO; idx += NTHREADS) wout_s[idx] = p.W_out[idx];
    if (tid < NYO) bout_s[tid] = p.b_out[tid];
    float blat = p.b_lat[tx];
    __syncthreads();

    // ---------------- latent + out heads per level ----------------
    for (int l = 0; l < LEV; l++) {
        for (int idx = tid; idx < TB * NH; idx += NTHREADS) {
            int r = idx >> 6, k = idx & 63;
            xh[r * KDIM + k] = g_scratch[((size_t)l * BATCH + b0 + r) * NH + k];
        }
        __syncthreads();
        // latent[r][tx] over 8 rows per thread (all 256 threads: 4 row groups x 64 cols)
        {
            float accL[8];
#pragma unroll
            for (int u = 0; u < 8; u++) accL[u] = blat;
            for (int kq = 0; kq < NH / 4; kq++) {
                float4 wv = *(const float4*)&W_s[tx * KDIM + kq * 4];
#pragma unroll
                for (int u = 0; u < 8; u++) {
                    float4 xv = *(const float4*)&xh[(ty * 8 + u) * KDIM + kq * 4];
                    accL[u] = fmaf(xv.x, wv.x, accL[u]);
                    accL[u] = fmaf(xv.y, wv.y, accL[u]);
                    accL[u] = fmaf(xv.z, wv.z, accL[u]);
                    accL[u] = fmaf(xv.w, wv.w, accL[u]);
                }
            }
#pragma unroll
            for (int u = 0; u < 8; u++) {
                int r = ty * 8 + u;
                size_t b = b0 + r;
                gacc[r * NH + tx] = accL[u];
                p.out[OFF_MEM + (b * LEV + l) * NMEM + tx] = accL[u];
            }
        }
        __syncthreads();
        // out head: (TB x 4), K = 64 over latent in gacc
        if (tid < TB * NYO) {
            int r = tid >> 2, y = tid & 3;
            float a = bout_s[y];
            for (int mq = 0; mq < NH / 4; mq++) {
                float4 lv4 = *(const float4*)&gacc[r * NH + mq * 4];
                a = fmaf(lv4.x, wout_s[(mq * 4 + 0) * NYO + y], a);
                a = fmaf(lv4.y, wout_s[(mq * 4 + 1) * NYO + y], a);
                a = fmaf(lv4.z, wout_s[(mq * 4 + 2) * NYO + y], a);
                a = fmaf(lv4.w, wout_s[(mq * 4 + 3) * NYO + y], a);
            }
            p.out[(size_t)(b0 + r) * (LEV * NYO) + l * NYO + y] = a;
        }
        __syncthreads();
    }
}

extern "C" void kernel_launch(void* const* d_in, const int* in_sizes, int n_in,
                              void* d_out, int out_size) {
    Params p;
    p.inputs_main = (const float*)d_in[0];
    p.inputs_aux  = (const float*)d_in[1];
    p.rnn1_mem    = (const float*)d_in[2];
    p.eps1        = (const float*)d_in[3];
    p.eps2        = (const float*)d_in[4];
    p.eps_sfc     = (const float*)d_in[5];
    p.W_sfc   = (const float*)d_in[6];  p.b_sfc   = (const float*)d_in[7];
    p.W_sfc2  = (const float*)d_in[8];  p.b_sfc2  = (const float*)d_in[9];
    p.W_toa   = (const float*)d_in[10]; p.b_toa   = (const float*)d_in[11];
    p.W_toa2  = (const float*)d_in[12]; p.b_toa2  = (const float*)d_in[13];
    p.Wx1  = (const float*)d_in[14]; p.Wh1  = (const float*)d_in[15];
    p.Wxs1 = (const float*)d_in[16]; p.Whs1 = (const float*)d_in[17];
    p.Wx2  = (const float*)d_in[18]; p.Wh2  = (const float*)d_in[19];
    p.Wxs2 = (const float*)d_in[20]; p.Whs2 = (const float*)d_in[21];
    p.W_lat    = (const float*)d_in[22]; p.b_lat    = (const float*)d_in[23];
    p.W_out    = (const float*)d_in[24]; p.b_out    = (const float*)d_in[25];
    p.W_sfcout = (const float*)d_in[26]; p.b_sfcout = (const float*)d_in[27];
    p.W_mu     = (const float*)d_in[28]; p.b_mu     = (const float*)d_in[29];
    p.W_lv     = (const float*)d_in[30]; p.b_lv     = (const float*)d_in[31];
    p.out = (float*)d_out;

    cudaFuncSetAttribute(stochastic_rnn_kernel,
                         cudaFuncAttributeMaxDynamicSharedMemorySize, SMEM_BYTES);
    stochastic_rnn_kernel<<<NBLOCKS, NTHREADS, SMEM_BYTES>>>(p);
}

// round 3
// speedup vs baseline: 1.9647x; 1.9647x over previous
#include <cuda_runtime.h>
#include <math.h>

// Problem constants
#define LEV     60
#define BATCH   4096
#define NXI     4
#define NH      64
#define NMEM    64
#define NSFC    17
#define NYO     4
#define XW1     68          // NXI + NMEM
#define KDIM    132         // unified K (rnn1: 68+64, rnn2: 64+64 zero-padded to 132)
#define NG      256         // 4*NH gate columns
#define NWCOL   320         // gates (256) + logvar (64)
#define TB      32          // batch rows per block
#define NTHREADS 256
#define NBLOCKS (BATCH / TB)   // 128

// shared layout (floats): W_s[NWCOL][KDIM] | xh[TB][KDIM] | gacc[TB][NWCOL]
#define SM_W     (NWCOL * KDIM)            // 42240
#define SM_XH    (TB * KDIM)               // 4224
#define SM_GACC  (TB * NWCOL)              // 10240
#define SMEM_FLOATS (SM_W + SM_XH + SM_GACC)
#define SMEM_BYTES  (SMEM_FLOATS * 4)      // 226816 < 232448 opt-in limit

// output layout: out (B,L,NYO) || out_sfc (B,3) || new_mem (B,L,NMEM)
#define OFF_OUT  0
#define OFF_SFC  (BATCH * LEV * NYO)                 // 983040
#define OFF_MEM  (OFF_SFC + BATCH * 3)               // 995328

// inter-phase scratch: rnn1out then (overwritten in place) rnn2out, [level][batch][NH]
__device__ float g_scratch[LEV * BATCH * NH];

struct Params {
    const float *inputs_main, *inputs_aux, *rnn1_mem, *eps1, *eps2, *eps_sfc;
    const float *W_sfc, *b_sfc, *W_sfc2, *b_sfc2, *W_toa, *b_toa, *W_toa2, *b_toa2;
    const float *Wx1, *Wh1, *Wxs1, *Whs1, *Wx2, *Wh2, *Wxs2, *Whs2;
    const float *W_lat, *b_lat, *W_out, *b_out, *W_sfcout, *b_sfcout;
    const float *W_mu, *b_mu, *W_lv, *b_lv;
    float *out;
};

__device__ __forceinline__ float sigmoidf_(float x) {
    return __fdividef(1.0f, 1.0f + __expf(-x));
}
__device__ __forceinline__ float tanhf_(float x) {
    float ax = fabsf(x);
    float e  = __expf(2.0f * ax);                    // overflow -> +inf -> term -> 0
    float t  = 1.0f - __fdividef(2.0f, e + 1.0f);
    return copysignf(t, x);
}

// packed fp32x2 FMA (Blackwell): d = a*b + c elementwise on {lo,hi}
__device__ __forceinline__ unsigned long long fma2_(unsigned long long a,
                                                    unsigned long long b,
                                                    unsigned long long c) {
    unsigned long long d;
    asm("fma.rn.f32x2 %0, %1, %2, %3;" : "=l"(d) : "l"(a), "l"(b), "l"(c));
    return d;
}
__device__ __forceinline__ float pairsum_(unsigned long long v) {
    float lo = __int_as_float((int)(v & 0xffffffffull));
    float hi = __int_as_float((int)(v >> 32));
    return lo + hi;
}

// Fused GEMM: gacc[r][j] = sum_k xh[r][k] * W_s[j][k], r<TB, j<NWCOL, K=KDIM.
// thread (tx = tid&63, ty = tid>>6) owns cols {c*64+tx} (c=0..4) x rows {ty*8+u} (u=0..7).
// K packed in pairs via fma.rn.f32x2 (even/odd-k partial sums, combined at the end).
__device__ __forceinline__ void gemm_step(const float* __restrict__ W_s,
                                          const float* __restrict__ xh,
                                          float* __restrict__ gacc,
                                          int tx, int ty) {
    unsigned long long acc[8][5];
#pragma unroll
    for (int u = 0; u < 8; u++)
#pragma unroll
        for (int c = 0; c < 5; c++) acc[u][c] = 0ull;

#pragma unroll 1
    for (int kq = 0; kq < KDIM / 4; kq++) {
        ulonglong2 wv[5];
#pragma unroll
        for (int c = 0; c < 5; c++)
            wv[c] = *(const ulonglong2*)&W_s[(c * 64 + tx) * KDIM + kq * 4];
#pragma unroll
        for (int u = 0; u < 8; u++) {
            ulonglong2 xv = *(const ulonglong2*)&xh[(ty * 8 + u) * KDIM + kq * 4];
#pragma unroll
            for (int c = 0; c < 5; c++) {
                acc[u][c] = fma2_(xv.x, wv[c].x, acc[u][c]);
                acc[u][c] = fma2_(xv.y, wv[c].y, acc[u][c]);
            }
        }
    }
#pragma unroll
    for (int u = 0; u < 8; u++)
#pragma unroll
        for (int c = 0; c < 5; c++)
            gacc[(ty * 8 + u) * NWCOL + c * 64 + tx] = pairsum_(acc[u][c]);
}

// LSTM pointwise for thread's 8 elems (row pr, cols pj0..pj0+7). c kept in regs.
// eps supplied in registers (prefetched before the GEMM).
__device__ __forceinline__ void pointwise_step(float* __restrict__ xh,
                                               const float* __restrict__ gacc,
                                               float* __restrict__ c_reg,
                                               int pr, int pj0, int hoff,
                                               const float* __restrict__ ge,
                                               float* __restrict__ hout_ptr) {
    const float* g = gacc + pr * NWCOL + pj0;
    float gi[8], gf[8], gg[8], go[8], gv[8];
    *(float4*)&gi[0] = *(const float4*)(g);        *(float4*)&gi[4] = *(const float4*)(g + 4);
    *(float4*)&gf[0] = *(const float4*)(g + 64);   *(float4*)&gf[4] = *(const float4*)(g + 68);
    *(float4*)&gg[0] = *(const float4*)(g + 128);  *(float4*)&gg[4] = *(const float4*)(g + 132);
    *(float4*)&go[0] = *(const float4*)(g + 192);  *(float4*)&go[4] = *(const float4*)(g + 196);
    *(float4*)&gv[0] = *(const float4*)(g + 256);  *(float4*)&gv[4] = *(const float4*)(g + 260);

    float hs[8];
#pragma unroll
    for (int u = 0; u < 8; u++) {
        float iv = sigmoidf_(gi[u]);
        float fv = sigmoidf_(gf[u]);
        float gvv = tanhf_(gg[u]);
        float ov = sigmoidf_(go[u]);
        float c  = fv * c_reg[u] + iv * gvv;
        c_reg[u] = c;
        float h  = ov * tanhf_(c) + ge[u] * __expf(0.5f * gv[u]);
        xh[pr * KDIM + hoff + pj0 + u] = h;
        hs[u] = h;
    }
    *(float4*)(hout_ptr)     = *(const float4*)&hs[0];
    *(float4*)(hout_ptr + 4) = *(const float4*)&hs[4];
}

extern __shared__ float smem[];

__global__ __launch_bounds__(NTHREADS, 1)
void stochastic_rnn_kernel(Params p) {
    const int tid = threadIdx.x;
    const int b0  = blockIdx.x * TB;

    float* W_s  = smem;
    float* xh   = smem + SM_W;
    float* gacc = xh + SM_XH;

    // pointwise identity: (row pr, cols pj0..pj0+7)
    const int pr  = tid >> 3;
    const int pj0 = (tid & 7) * 8;
    // gemm identity
    const int tx = tid & 63;
    const int ty = tid >> 6;
    // rnn1 x-prefetch identity: row xr_r, 8 mem-cols at lane8*8
    const int xr_r   = tid >> 3;
    const int lane8  = tid & 7;

    float c_reg[8];

    // ---------------- load rnn1 weights (transposed, fused) ----------------
    for (int idx = tid; idx < NWCOL * KDIM; idx += NTHREADS) {
        int j = idx / KDIM, k = idx % KDIM;
        float v;
        if (j < NG) v = (k < XW1) ? p.Wx1[k * NG + j] : p.Wh1[(k - XW1) * NG + j];
        else {
            int jj = j - NG;
            v = (k < XW1) ? p.Wxs1[k * NH + jj] : p.Whs1[(k - XW1) * NH + jj];
        }
        W_s[idx] = v;
    }

    // ---------------- rnn1 initial h, c from surface MLPs ----------------
    {
        const float* auxrow = p.inputs_aux + (size_t)(b0 + pr) * NSFC;
#pragma unroll
        for (int u = 0; u < 8; u++) {
            int j = pj0 + u;
            float ah = p.b_sfc[j], ac = p.b_sfc2[j];
            for (int k = 0; k < NSFC; k++) {
                float a = auxrow[k];
                ah = fmaf(a, p.W_sfc[k * NH + j], ah);
                ac = fmaf(a, p.W_sfc2[k * NH + j], ac);
            }
            xh[pr * KDIM + XW1 + j] = tanhf_(ah);
            c_reg[u] = tanhf_(ac);
        }
    }

    // ---------------- rnn1: bottom-up over levels, with x/eps prefetch ----------------
    float mr[8];            // prefetched rnn1_mem chunk
    float xm[4];            // prefetched inputs_main chunk (lane8==0 only)
    {
        int l0 = LEV - 1;
        size_t rowbase = ((size_t)(b0 + xr_r) * LEV + l0);
        *(float4*)&mr[0] = *(const float4*)&p.rnn1_mem[rowbase * NMEM + lane8 * 8];
        *(float4*)&mr[4] = *(const float4*)&p.rnn1_mem[rowbase * NMEM + lane8 * 8 + 4];
        if (lane8 == 0)
            *(float4*)&xm[0] = *(const float4*)&p.inputs_main[rowbase * NXI];
    }

    for (int s = 0; s < LEV; s++) {
        int l = LEV - 1 - s;
        // commit prefetched x into xh
        *(float4*)&xh[xr_r * KDIM + NXI + lane8 * 8]     = *(const float4*)&mr[0];
        *(float4*)&xh[xr_r * KDIM + NXI + lane8 * 8 + 4] = *(const float4*)&mr[4];
        if (lane8 == 0)
            *(float4*)&xh[xr_r * KDIM] = *(const float4*)&xm[0];
        __syncthreads();

        // issue this-step eps loads + next-step x loads (latency hidden by GEMM)
        float ge[8];
        {
            const float* ep = p.eps1 + ((size_t)s * BATCH + b0 + pr) * NH + pj0;
            *(float4*)&ge[0] = *(const float4*)(ep);
            *(float4*)&ge[4] = *(const float4*)(ep + 4);
        }
        if (s + 1 < LEV) {
            int ln = l - 1;
            size_t rowbase = ((size_t)(b0 + xr_r) * LEV + ln);
            *(float4*)&mr[0] = *(const float4*)&p.rnn1_mem[rowbase * NMEM + lane8 * 8];
            *(float4*)&mr[4] = *(const float4*)&p.rnn1_mem[rowbase * NMEM + lane8 * 8 + 4];
            if (lane8 == 0)
                *(float4*)&xm[0] = *(const float4*)&p.inputs_main[rowbase * NXI];
        }

        gemm_step(W_s, xh, gacc, tx, ty);
        __syncthreads();
        pointwise_step(xh, gacc, c_reg, pr, pj0, XW1, ge,
                       g_scratch + ((size_t)l * BATCH + b0 + pr) * NH + pj0);
        __syncthreads();
    }

    // ---------------- load rnn2 weights (K padded 128->132 with zeros) ----------------
    for (int idx = tid; idx < NWCOL * KDIM; idx += NTHREADS) {
        int j = idx / KDIM, k = idx % KDIM;
        float v = 0.0f;
        if (j < NG) {
            if (k < NH)            v = p.Wx2[k * NG + j];
            else if (k < 2 * NH)   v = p.Wh2[(k - NH) * NG + j];
        } else {
            int jj = j - NG;
            if (k < NH)            v = p.Wxs2[k * NH + jj];
            else if (k < 2 * NH)   v = p.Whs2[(k - NH) * NH + jj];
        }
        W_s[idx] = v;
    }
    // zero xh pad columns 128..131
    for (int idx = tid; idx < TB * 4; idx += NTHREADS)
        xh[(idx >> 2) * KDIM + 128 + (idx & 3)] = 0.0f;

    // rnn2 initial h, c from TOA MLPs (inputs_toa = aux[:,1], aux[:,6])
    {
        float x0 = p.inputs_aux[(size_t)(b0 + pr) * NSFC + 1];
        float x1 = p.inputs_aux[(size_t)(b0 + pr) * NSFC + 6];
#pragma unroll
        for (int u = 0; u < 8; u++) {
            int j = pj0 + u;
            float ah = fmaf(x0, p.W_toa[j],  fmaf(x1, p.W_toa[NH + j],  p.b_toa[j]));
            float ac = fmaf(x0, p.W_toa2[j], fmaf(x1, p.W_toa2[NH + j], p.b_toa2[j]));
            xh[pr * KDIM + NH + j] = tanhf_(ah);
            c_reg[u] = tanhf_(ac);
        }
    }

    // ---------------- rnn2: top-down over levels; overwrite scratch in place ----------------
    float hr[8];
    {
        const float* sp = g_scratch + ((size_t)0 * BATCH + b0 + pr) * NH + pj0;
        *(float4*)&hr[0] = *(const float4*)(sp);
        *(float4*)&hr[4] = *(const float4*)(sp + 4);
    }
    for (int s = 0; s < LEV; s++) {
        *(float4*)&xh[pr * KDIM + pj0]     = *(const float4*)&hr[0];
        *(float4*)&xh[pr * KDIM + pj0 + 4] = *(const float4*)&hr[4];
        __syncthreads();

        float ge[8];
        {
            const float* ep = p.eps2 + ((size_t)s * BATCH + b0 + pr) * NH + pj0;
            *(float4*)&ge[0] = *(const float4*)(ep);
            *(float4*)&ge[4] = *(const float4*)(ep + 4);
        }
        if (s + 1 < LEV) {
            const float* sp = g_scratch + ((size_t)(s + 1) * BATCH + b0 + pr) * NH + pj0;
            *(float4*)&hr[0] = *(const float4*)(sp);
            *(float4*)&hr[4] = *(const float4*)(sp + 4);
        }

        gemm_step(W_s, xh, gacc, tx, ty);
        __syncthreads();
        pointwise_step(xh, gacc, c_reg, pr, pj0, NH, ge,
                       g_scratch + ((size_t)s * BATCH + b0 + pr) * NH + pj0);
        __syncthreads();
    }

    // ---------------- surface heads from last hidden (in xh cols 64..127) ----------------
    if (tid < TB) {
        int r = tid;
        size_t b = b0 + r;
        float rad = p.b_sfcout[0];
        float mu0 = p.b_mu[0], mu1 = p.b_mu[1];
        float lv0 = p.b_lv[0], lv1 = p.b_lv[1];
        for (int k = 0; k < NH; k++) {
            float h = xh[r * KDIM + NH + k];
            rad = fmaf(h, p.W_sfcout[k], rad);
            mu0 = fmaf(h, p.W_mu[k * 2 + 0], mu0);
            mu1 = fmaf(h, p.W_mu[k * 2 + 1], mu1);
            lv0 = fmaf(h, p.W_lv[k * 2 + 0], lv0);
            lv1 = fmaf(h, p.W_lv[k * 2 + 1], lv1);
        }
        float e0 = p.eps_sfc[b * 2 + 0], e1 = p.eps_sfc[b * 2 + 1];
        p.out[OFF_SFC + b * 3 + 0] = mu0 + e0 * __expf(0.5f * lv0);
        p.out[OFF_SFC + b * 3 + 1] = mu1 + e1 * __expf(0.5f * lv1);
        p.out[OFF_SFC + b * 3 + 2] = rad;
    }

    // ---------------- load W_lat (transposed) + W_out/b_out into smem ----------------
    for (int idx = tid; idx < NH * NH; idx += NTHREADS) {
        int m = idx >> 6, k = idx & 63;
        W_s[m * KDIM + k] = p.W_lat[k * NH + m];
    }
    float* wout_s = W_s + NH * KDIM;         // 256 floats
    float* bout_s = wout_s + NH * NYO;       // 4 floats
    for (int idx = tid; idx < NH * NYO; idx += NTHREADS) wout_s[idx] = p.W_out[idx];
    if (tid < NYO) bout_s[tid] = p.b_out[tid];
    float blat = p.b_lat[tx];
    __syncthreads();

    // ---------------- latent + out heads per level (prefetched, f32x2) ----------------
    float lr[8];
    {
        const float* sp = g_scratch + ((size_t)0 * BATCH + b0 + pr) * NH + pj0;
        *(float4*)&lr[0] = *(const float4*)(sp);
        *(float4*)&lr[4] = *(const float4*)(sp + 4);
    }
    for (int l = 0; l < LEV; l++) {
        *(float4*)&xh[pr * KDIM + pj0]     = *(const float4*)&lr[0];
        *(float4*)&xh[pr * KDIM + pj0 + 4] = *(const float4*)&lr[4];
        __syncthreads();
        if (l + 1 < LEV) {
            const float* sp = g_scratch + ((size_t)(l + 1) * BATCH + b0 + pr) * NH + pj0;
            *(float4*)&lr[0] = *(const float4*)(sp);
            *(float4*)&lr[4] = *(const float4*)(sp + 4);
        }
        // latent[r][tx] over 8 rows per thread
        {
            unsigned long long accL[8];
#pragma unroll
            for (int u = 0; u < 8; u++) accL[u] = 0ull;
#pragma unroll 1
            for (int kq = 0; kq < NH / 4; kq++) {
                ulonglong2 wv = *(const ulonglong2*)&W_s[tx * KDIM + kq * 4];
#pragma unroll
                for (int u = 0; u < 8; u++) {
                    ulonglong2 xv = *(const ulonglong2*)&xh[(ty * 8 + u) * KDIM + kq * 4];
                    accL[u] = fma2_(xv.x, wv.x, accL[u]);
                    accL[u] = fma2_(xv.y, wv.y, accL[u]);
                }
            }
#pragma unroll
            for (int u = 0; u < 8; u++) {
                int r = ty * 8 + u;
                size_t b = b0 + r;
                float v = pairsum_(accL[u]) + blat;
                gacc[r * NH + tx] = v;
                p.out[OFF_MEM + (b * LEV + l) * NMEM + tx] = v;
            }
        }
        __syncthreads();
        // out head: (TB x 4), K = 64 over latent in gacc
        if (tid < TB * NYO) {
            int r = tid >> 2, y = tid & 3;
            float a = bout_s[y];
            for (int mq = 0; mq < NH / 4; mq++) {
                float4 lv4 = *(const float4*)&gacc[r * NH + mq * 4];
                a = fmaf(lv4.x, wout_s[(mq * 4 + 0) * NYO + y], a);
                a = fmaf(lv4.y, wout_s[(mq * 4 + 1) * NYO + y], a);
                a = fmaf(lv4.z, wout_s[(mq * 4 + 2) * NYO + y], a);
                a = fmaf(lv4.w, wout_s[(mq * 4 + 3) * NYO + y], a);
            }
            p.out[(size_t)(b0 + r) * (LEV * NYO) + l * NYO + y] = a;
        }
        __syncthreads();
    }
}

extern "C" void kernel_launch(void* const* d_in, const int* in_sizes, int n_in,
                              void* d_out, int out_size) {
    Params p;
    p.inputs_main = (const float*)d_in[0];
    p.inputs_aux  = (const float*)d_in[1];
    p.rnn1_mem    = (const float*)d_in[2];
    p.eps1        = (const float*)d_in[3];
    p.eps2        = (const float*)d_in[4];
    p.eps_sfc     = (const float*)d_in[5];
    p.W_sfc   = (const float*)d_in[6];  p.b_sfc   = (const float*)d_in[7];
    p.W_sfc2  = (const float*)d_in[8];  p.b_sfc2  = (const float*)d_in[9];
    p.W_toa   = (const float*)d_in[10]; p.b_toa   = (const float*)d_in[11];
    p.W_toa2  = (const float*)d_in[12]; p.b_toa2  = (const float*)d_in[13];
    p.Wx1  = (const float*)d_in[14]; p.Wh1  = (const float*)d_in[15];
    p.Wxs1 = (const float*)d_in[16]; p.Whs1 = (const float*)d_in[17];
    p.Wx2  = (const float*)d_in[18]; p.Wh2  = (const float*)d_in[19];
    p.Wxs2 = (const float*)d_in[20]; p.Whs2 = (const float*)d_in[21];
    p.W_lat    = (const float*)d_in[22]; p.b_lat    = (const float*)d_in[23];
    p.W_out    = (const float*)d_in[24]; p.b_out    = (const float*)d_in[25];
    p.W_sfcout = (const float*)d_in[26]; p.b_sfcout = (const float*)d_in[27];
    p.W_mu     = (const float*)d_in[28]; p.b_mu     = (const float*)d_in[29];
    p.W_lv     = (const float*)d_in[30]; p.b_lv     = (const float*)d_in[31];
    p.out = (float*)d_out;

    cudaFuncSetAttribute(stochastic_rnn_kernel,
                         cudaFuncAttributeMaxDynamicSharedMemorySize, SMEM_BYTES);
    stochastic_rnn_kernel<<<NBLOCKS, NTHREADS, SMEM_BYTES>>>(p);
}